// round 1
// baseline (speedup 1.0000x reference)
#include <cuda_runtime.h>
#include <cuda_bf16.h>

// SimpleRNN: h_t = tanh(a*x_t + b*h_{t-1} + c), output h_T per row.
// Contraction-truncated: only the last K = ceil(18.5 / -ln|b|) steps matter
// to 1e-8 absolute (|dh_t/dh_{t-1}| <= |b| < 1, |h| <= 1). K computed on
// device from the inputs -> deterministic & graph-capturable.
//
// Inner recurrence on r = 1/(exp2(z)+1), h = 1-2r:
//   z_{t+1} = M*r_t + W_{t+1},  M = -4*log2e*b,  W_t = 2*log2e*(b + a*x_t + c)
// Chain per step: FFMA(4) + EX2(16) + FADD(4) + RCP(16) ~= 40 cycles.

#define RNN_T 4096

__device__ __forceinline__ float ex2_approx(float x) {
    float y;
    asm("ex2.approx.f32 %0, %1;" : "=f"(y) : "f"(x));
    return y;
}
__device__ __forceinline__ float rcp_approx(float x) {
    float y;
    asm("rcp.approx.f32 %0, %1;" : "=f"(y) : "f"(x));
    return y;
}

__global__ void __launch_bounds__(128)
simple_rnn_kernel(const float* __restrict__ x,
                  const float* __restrict__ w_ih,
                  const float* __restrict__ w_hh,
                  const float* __restrict__ b_ih,
                  const float* __restrict__ b_hh,
                  float* __restrict__ out,
                  int B) {
    int r = blockIdx.x * blockDim.x + threadIdx.x;
    if (r >= B) return;

    const float a = w_ih[0];
    const float b = w_hh[0];
    const float c = b_ih[0] + b_hh[0];

    // ---- truncation horizon K (uniform across threads) ----
    float ab = fabsf(b);
    float l  = __logf(ab);           // -inf for ab==0, ~0- for ab->1
    int K;
    if (!(l < -1e-9f)) {
        K = RNN_T;                   // |b| >= 1 (or degenerate): full scan
    } else {
        float kf = 18.5f / (-l);     // |b|^K <= e^-18.5 ~ 9e-9
        K = (kf >= (float)RNN_T) ? RNN_T : (int)kf + 1;
    }
    if (K < 1) K = 1;
    if (K > RNN_T) K = RNN_T;

    const float L2 = 2.0f * 1.4426950408889634f;   // 2*log2(e)
    const float A2 = L2 * a;
    const float C2 = L2 * (b + c);
    const float M  = -2.0f * L2 * b;               // -4*log2e*b

    const float* __restrict__ xr = x + (size_t)r * RNN_T + (RNN_T - K);

    float rr = 0.5f;                 // corresponds to h = 0

    int t = 0;
    // main loop: unroll 8; W precompute is off the serial chain -> MLP for loads
    for (; t + 8 <= K; t += 8) {
        float w0 = fmaf(xr[t + 0], A2, C2);
        float w1 = fmaf(xr[t + 1], A2, C2);
        float w2 = fmaf(xr[t + 2], A2, C2);
        float w3 = fmaf(xr[t + 3], A2, C2);
        float w4 = fmaf(xr[t + 4], A2, C2);
        float w5 = fmaf(xr[t + 5], A2, C2);
        float w6 = fmaf(xr[t + 6], A2, C2);
        float w7 = fmaf(xr[t + 7], A2, C2);

        float z;
        z = fmaf(M, rr, w0); rr = rcp_approx(ex2_approx(z) + 1.0f);
        z = fmaf(M, rr, w1); rr = rcp_approx(ex2_approx(z) + 1.0f);
        z = fmaf(M, rr, w2); rr = rcp_approx(ex2_approx(z) + 1.0f);
        z = fmaf(M, rr, w3); rr = rcp_approx(ex2_approx(z) + 1.0f);
        z = fmaf(M, rr, w4); rr = rcp_approx(ex2_approx(z) + 1.0f);
        z = fmaf(M, rr, w5); rr = rcp_approx(ex2_approx(z) + 1.0f);
        z = fmaf(M, rr, w6); rr = rcp_approx(ex2_approx(z) + 1.0f);
        z = fmaf(M, rr, w7); rr = rcp_approx(ex2_approx(z) + 1.0f);
    }
    for (; t < K; t++) {
        float w = fmaf(xr[t], A2, C2);
        float z = fmaf(M, rr, w);
        rr = rcp_approx(ex2_approx(z) + 1.0f);
    }

    out[r] = fmaf(-2.0f, rr, 1.0f);  // h_T = 1 - 2*r
}

extern "C" void kernel_launch(void* const* d_in, const int* in_sizes, int n_in,
                              void* d_out, int out_size) {
    const float* x    = (const float*)d_in[0];
    const float* w_ih = (const float*)d_in[1];
    const float* w_hh = (const float*)d_in[2];
    const float* b_ih = (const float*)d_in[3];
    const float* b_hh = (const float*)d_in[4];
    float* out = (float*)d_out;

    int B = out_size;                 // output is [B, 1] float32
    int threads = 128;
    int blocks = (B + threads - 1) / threads;
    simple_rnn_kernel<<<blocks, threads>>>(x, w_ih, w_hh, b_ih, b_hh, out, B);
}